// round 1
// baseline (speedup 1.0000x reference)
#include <cuda_runtime.h>
#include <cstdint>

#define U_ 128
#define C_ 64
#define B_ 16
#define T_ 128
#define RANKS 8         // CTAs per cluster (one cluster per batch)
#define IPC 16          // pre-rows / post-cols owned per CTA
#define CPC 8           // sensory rows owned per CTA
#define NTH 256
#define UNFOLDS 6
#define EPS_ 1e-8f
#define L2E 1.4426950408889634f

// ---------------- device scratch (no allocations allowed) ----------------
__device__ float g_rsK[U_*U_];   // -sigma * log2e
__device__ float g_rcK[U_*U_];   //  sigma * mu * log2e
__device__ float g_rwE[U_*U_];   //  softplus(w) * erev   (sign folded)
__device__ float g_ssK[C_*U_];   // -ssigma * iw * log2e
__device__ float g_scK[C_*U_];   //  ssigma * log2e * (smu - ib)
__device__ float g_swE[C_*U_];   //  softplus(sw) * serev
__device__ float g_cmt[U_];      //  softplus(cm) * 6
__device__ float g_AA[U_];       //  cmt + softplus(gleak)
__device__ float g_CC[U_];       //  softplus(gleak) * vleak

__device__ __forceinline__ float softplus_f(float x) {
    return fmaxf(x, 0.0f) + log1pf(expf(-fabsf(x)));
}

__global__ void ltc_prep(const float* __restrict__ sigma, const float* __restrict__ mu,
                         const float* __restrict__ w,     const float* __restrict__ erev,
                         const float* __restrict__ ssig,  const float* __restrict__ smu,
                         const float* __restrict__ sw,    const float* __restrict__ serev,
                         const float* __restrict__ iw,    const float* __restrict__ ib,
                         const float* __restrict__ gleak, const float* __restrict__ vleak,
                         const float* __restrict__ cm)
{
    int idx = blockIdx.x * blockDim.x + threadIdx.x;
    if (idx < U_*U_) {
        float sg = sigma[idx];
        g_rsK[idx] = -sg * L2E;
        g_rcK[idx] =  sg * mu[idx] * L2E;
        g_rwE[idx] =  softplus_f(w[idx]) * erev[idx];
    }
    if (idx < C_*U_) {
        int c = idx / U_;
        float sg = ssig[idx];
        g_ssK[idx] = -sg * L2E * iw[c];
        g_scK[idx] =  sg * L2E * (smu[idx] - ib[c]);
        g_swE[idx] =  softplus_f(sw[idx]) * serev[idx];
    }
    if (idx < U_) {
        float gl  = softplus_f(gleak[idx]);
        float cmt = softplus_f(cm[idx]) * (float)UNFOLDS;
        g_cmt[idx] = cmt;
        g_AA[idx]  = cmt + gl;
        g_CC[idx]  = gl * vleak[idx];
    }
}

// ---------------- PTX helpers ----------------
__device__ __forceinline__ uint32_t smem_u32(const void* p) {
    uint32_t a;
    asm("{ .reg .u64 t; cvta.to.shared.u64 t, %1; cvt.u32.u64 %0, t; }" : "=r"(a) : "l"(p));
    return a;
}
__device__ __forceinline__ uint32_t mapa_u32(uint32_t a, uint32_t r) {
    uint32_t o;
    asm("mapa.shared::cluster.u32 %0, %1, %2;" : "=r"(o) : "r"(a), "r"(r));
    return o;
}
__device__ __forceinline__ void st_cluster_f2(uint32_t a, float xx, float yy) {
    asm volatile("st.shared::cluster.v2.f32 [%0], {%1, %2};" :: "r"(a), "f"(xx), "f"(yy) : "memory");
}
__device__ __forceinline__ void cluster_sync_() {
    asm volatile("barrier.cluster.arrive.aligned;" ::: "memory");
    asm volatile("barrier.cluster.wait.aligned;"   ::: "memory");
}
__device__ __forceinline__ float ex2f_(float x) { float y; asm("ex2.approx.f32 %0, %1;" : "=f"(y) : "f"(x)); return y; }
__device__ __forceinline__ float rcpf_(float x) { float y; asm("rcp.approx.f32 %0, %1;" : "=f"(y) : "f"(x)); return y; }

// ---------------- main kernel: one cluster (8 CTAs) per batch ----------------
__global__ void __cluster_dims__(RANKS, 1, 1) __launch_bounds__(NTH, 1)
ltc_main(const float* __restrict__ x, const float* __restrict__ h0,
         const float* __restrict__ ow, const float* __restrict__ ob,
         float* __restrict__ out)
{
    __shared__ float2 sPart[2][16][IPC];   // [buf][source slot][local j] partials
    __shared__ float2 sPartS[16][IPC];     // sensory partials
    __shared__ float  sV[IPC];             // my v chunk (j == i chunk)
    __shared__ float  sSN[IPC], sSD[IPC];  // sensory sums for my j's
    __shared__ float  sX[T_][CPC];         // staged x for my sensory rows
    __shared__ float  pCMT[IPC], pA[IPC], pC[IPC], pOW[IPC], pOB[IPC];

    const int tid  = threadIdx.x;
    const int b    = blockIdx.x / RANKS;
    const int rank = blockIdx.x % RANKS;
    const int j    = tid & (U_ - 1);   // post-neuron handled by this thread
    const int g    = tid >> 7;         // 0/1: which half of the i-range
    const int j0   = rank * IPC;
    const int dest = j >> 4;           // cluster rank owning column j
    const int slot = rank * 2 + g;     // source slot in dest's partial buffer
    const int jj   = j & 15;

    // ---- preload weights into registers (live across entire T loop) ----
    float rs[8], rc[8], rw[8];
    const int iBase = rank * IPC + g * 8;
    #pragma unroll
    for (int k = 0; k < 8; k++) {
        int idx = (iBase + k) * U_ + j;
        rs[k] = g_rsK[idx]; rc[k] = g_rcK[idx]; rw[k] = g_rwE[idx];
    }
    float ssk[4], sck[4], swe[4];
    const int cBase = rank * CPC + g * 4;
    #pragma unroll
    for (int k = 0; k < 4; k++) {
        int idx = (cBase + k) * U_ + j;
        ssk[k] = g_ssK[idx]; sck[k] = g_scK[idx]; swe[k] = g_swE[idx];
    }
    // stage my x slice: x[b, :, c0:c0+8]
    for (int idx = tid; idx < T_ * CPC; idx += NTH) {
        int t = idx >> 3, k = idx & 7;
        sX[t][k] = x[(b * T_ + t) * C_ + rank * CPC + k];
    }
    if (tid < IPC) {
        int jg = j0 + tid;
        sV[tid]   = h0[b * U_ + jg];
        pCMT[tid] = g_cmt[jg];
        pA[tid]   = g_AA[jg];
        pC[tid]   = g_CC[jg];
        pOW[tid]  = ow[jg];
        pOB[tid]  = ob[jg];
    }
    __syncthreads();

    // precompute remote DSMEM addresses for my partial slot
    const uint32_t addrS  = mapa_u32(smem_u32(&sPartS[slot][jj]),  (uint32_t)dest);
    const uint32_t addrP0 = mapa_u32(smem_u32(&sPart[0][slot][jj]), (uint32_t)dest);
    const uint32_t addrP1 = mapa_u32(smem_u32(&sPart[1][slot][jj]), (uint32_t)dest);

    for (int t = 0; t < T_; t++) {
        // ---- sensory synapses (constant across unfolds) ----
        float xn = 0.f, xd = 0.f;
        #pragma unroll
        for (int k = 0; k < 4; k++) {
            float xv = sX[t][g * 4 + k];
            float e  = ex2f_(fmaf(ssk[k], xv, sck[k]));   // exp(-arg)
            float r  = rcpf_(1.0f + e);                    // sigmoid
            float p  = swe[k] * r;                         // signed activation
            xn += p; xd += fabsf(p);
        }
        st_cluster_f2(addrS, xn, xd);
        cluster_sync_();
        if (tid < IPC) {
            float n = 0.f, d = 0.f;
            #pragma unroll
            for (int s = 0; s < 16; s++) { float2 pp = sPartS[s][tid]; n += pp.x; d += pp.y; }
            sSN[tid] = n; sSD[tid] = d;
        }

        // ---- 6 ODE unfolds ----
        #pragma unroll
        for (int u = 0; u < UNFOLDS; u++) {
            float rn = 0.f, rd = 0.f;
            #pragma unroll
            for (int k = 0; k < 8; k++) {
                float vi = sV[g * 8 + k];                  // broadcast LDS
                float e  = ex2f_(fmaf(rs[k], vi, rc[k]));
                float r  = rcpf_(1.0f + e);
                float p  = rw[k] * r;
                rn += p; rd += fabsf(p);
            }
            st_cluster_f2((u & 1) ? addrP1 : addrP0, rn, rd);
            cluster_sync_();                               // peers' partials now visible
            if (tid < IPC) {
                float n = sSN[tid], d = sSD[tid];
                #pragma unroll
                for (int s = 0; s < 16; s++) { float2 pp = sPart[u & 1][s][tid]; n += pp.x; d += pp.y; }
                float vv  = sV[tid];
                float num = fmaf(pCMT[tid], vv, pC[tid]) + n;
                float den = pA[tid] + d + EPS_;
                sV[tid] = num / den;                       // precise div, 16 lanes only
            }
            __syncthreads();                               // publish new v chunk
        }

        // ---- readout for this step ----
        if (tid < IPC) {
            out[(b * T_ + t) * U_ + j0 + tid] = fmaf(sV[tid], pOW[tid], pOB[tid]);
        }
    }
    // ---- h_final appended after readout block ----
    if (tid < IPC) {
        out[B_ * T_ * U_ + b * U_ + j0 + tid] = sV[tid];
    }
}

// ---------------- launch ----------------
extern "C" void kernel_launch(void* const* d_in, const int* in_sizes, int n_in,
                              void* d_out, int out_size)
{
    const float* x     = (const float*)d_in[0];
    const float* h0    = (const float*)d_in[1];
    const float* gleak = (const float*)d_in[2];
    const float* vleak = (const float*)d_in[3];
    const float* cm    = (const float*)d_in[4];
    const float* sigma = (const float*)d_in[5];
    const float* mu    = (const float*)d_in[6];
    const float* w     = (const float*)d_in[7];
    const float* erev  = (const float*)d_in[8];
    const float* ssig  = (const float*)d_in[9];
    const float* smu   = (const float*)d_in[10];
    const float* sw    = (const float*)d_in[11];
    const float* serev = (const float*)d_in[12];
    const float* iw    = (const float*)d_in[13];
    const float* ib    = (const float*)d_in[14];
    const float* ow    = (const float*)d_in[15];
    const float* ob    = (const float*)d_in[16];

    ltc_prep<<<64, 256>>>(sigma, mu, w, erev, ssig, smu, sw, serev, iw, ib, gleak, vleak, cm);
    ltc_main<<<B_ * RANKS, NTH>>>(x, h0, ow, ob, (float*)d_out);
}

// round 2
// speedup vs baseline: 1.3471x; 1.3471x over previous
#include <cuda_runtime.h>
#include <cstdint>

#define U_ 128
#define C_ 64
#define B_ 16
#define T_ 128
#define RANKS 8         // CTAs per cluster (one cluster per batch)
#define IPC 16          // post-cols (and pre-rows) owned per CTA
#define CPC 8           // sensory channels owned per CTA
#define NTH 128
#define UNFOLDS 6
#define EPS_ 1e-8f
#define L2E 1.4426950408889634f

// bytes arriving at each dest CTA per reduction round: 8 ranks * 16 jj * 8B
#define TX_REC 1024u
#define TX_SEN 1024u

// ---------------- device scratch (no allocations allowed) ----------------
__device__ float g_rsK[U_*U_];   // -sigma * log2e
__device__ float g_rcK[U_*U_];   //  sigma * mu * log2e
__device__ float g_rwE[U_*U_];   //  softplus(w) * erev   (sign folded)
__device__ float g_ssK[C_*U_];   // -ssigma * iw * log2e
__device__ float g_scK[C_*U_];   //  ssigma * log2e * (smu - ib)
__device__ float g_swE[C_*U_];   //  softplus(sw) * serev
__device__ float g_cmt[U_];      //  softplus(cm) * 6
__device__ float g_AA[U_];       //  cmt + softplus(gleak)
__device__ float g_CC[U_];       //  softplus(gleak) * vleak

__device__ __forceinline__ float softplus_f(float x) {
    return fmaxf(x, 0.0f) + log1pf(expf(-fabsf(x)));
}

__global__ void ltc_prep(const float* __restrict__ sigma, const float* __restrict__ mu,
                         const float* __restrict__ w,     const float* __restrict__ erev,
                         const float* __restrict__ ssig,  const float* __restrict__ smu,
                         const float* __restrict__ sw,    const float* __restrict__ serev,
                         const float* __restrict__ iw,    const float* __restrict__ ib,
                         const float* __restrict__ gleak, const float* __restrict__ vleak,
                         const float* __restrict__ cm)
{
    int idx = blockIdx.x * blockDim.x + threadIdx.x;
    if (idx < U_*U_) {
        float sg = sigma[idx];
        g_rsK[idx] = -sg * L2E;
        g_rcK[idx] =  sg * mu[idx] * L2E;
        g_rwE[idx] =  softplus_f(w[idx]) * erev[idx];
    }
    if (idx < C_*U_) {
        int c = idx / U_;
        float sg = ssig[idx];
        g_ssK[idx] = -sg * L2E * iw[c];
        g_scK[idx] =  sg * L2E * (smu[idx] - ib[c]);
        g_swE[idx] =  softplus_f(sw[idx]) * serev[idx];
    }
    if (idx < U_) {
        float gl  = softplus_f(gleak[idx]);
        float cmt = softplus_f(cm[idx]) * (float)UNFOLDS;
        g_cmt[idx] = cmt;
        g_AA[idx]  = cmt + gl;
        g_CC[idx]  = gl * vleak[idx];
    }
}

// ---------------- PTX helpers ----------------
__device__ __forceinline__ uint32_t smem_u32(const void* p) {
    uint32_t a;
    asm("{ .reg .u64 t; cvta.to.shared.u64 t, %1; cvt.u32.u64 %0, t; }" : "=r"(a) : "l"(p));
    return a;
}
__device__ __forceinline__ uint32_t mapa_u32(uint32_t a, uint32_t r) {
    uint32_t o;
    asm("mapa.shared::cluster.u32 %0, %1, %2;" : "=r"(o) : "r"(a), "r"(r));
    return o;
}
__device__ __forceinline__ void cluster_sync_() {
    asm volatile("barrier.cluster.arrive.aligned;" ::: "memory");
    asm volatile("barrier.cluster.wait.aligned;"   ::: "memory");
}
__device__ __forceinline__ float ex2f_(float x) { float y; asm("ex2.approx.f32 %0, %1;" : "=f"(y) : "f"(x)); return y; }
__device__ __forceinline__ float rcpf_(float x) { float y; asm("rcp.approx.f32 %0, %1;" : "=f"(y) : "f"(x)); return y; }

__device__ __forceinline__ void mbar_init_(uint32_t mb, uint32_t cnt) {
    asm volatile("mbarrier.init.shared.b64 [%0], %1;" :: "r"(mb), "r"(cnt) : "memory");
}
__device__ __forceinline__ void mbar_expect_(uint32_t mb, uint32_t bytes) {
    asm volatile("mbarrier.arrive.expect_tx.shared.b64 _, [%0], %1;" :: "r"(mb), "r"(bytes) : "memory");
}
__device__ __forceinline__ void mbar_wait_(uint32_t mb, uint32_t parity) {
    uint32_t done;
    asm volatile(
        "{\n\t.reg .pred p;\n\t"
        "mbarrier.try_wait.parity.acquire.cta.shared::cta.b64 p, [%1], %2;\n\t"
        "selp.b32 %0, 1, 0, p;\n\t}"
        : "=r"(done) : "r"(mb), "r"(parity) : "memory");
    if (!done) {
        asm volatile(
            "{\n\t.reg .pred P1;\n\t"
            "WL_%=:\n\t"
            "mbarrier.try_wait.parity.acquire.cta.shared::cta.b64 P1, [%0], %1, 0x989680;\n\t"
            "@P1 bra.uni WD_%=;\n\t"
            "bra.uni WL_%=;\n\t"
            "WD_%=:\n\t}"
            :: "r"(mb), "r"(parity) : "memory");
    }
}
// async store of a float2 (packed b64) into a peer CTA's SMEM, tx-counted on peer mbarrier
__device__ __forceinline__ void st_async_f2(uint32_t addr, float xx, float yy, uint32_t mb) {
    uint64_t pk;
    asm("mov.b64 %0, {%1, %2};" : "=l"(pk) : "f"(xx), "f"(yy));
    asm volatile("st.async.shared::cluster.mbarrier::complete_tx::bytes.b64 [%0], %1, [%2];"
                 :: "r"(addr), "l"(pk), "r"(mb) : "memory");
}

// ---------------- main kernel: one cluster (8 CTAs) per batch ----------------
__global__ void __cluster_dims__(RANKS, 1, 1) __launch_bounds__(NTH, 1)
ltc_main(const float* __restrict__ x, const float* __restrict__ h0,
         const float* __restrict__ ow, const float* __restrict__ ob,
         float* __restrict__ out)
{
    // partial buffers: [jj][slot] rows padded to 10 float2 (80B) — float4-aligned, 2-way conflicts
    __shared__ float2 sPart[2][IPC][10];
    __shared__ float2 sSens[IPC][10];
    __shared__ float  sV[IPC];
    __shared__ float  sX[T_][CPC];
    __shared__ float  pCMT[IPC], pA[IPC], pC[IPC], pOW[IPC], pOB[IPC];
    __shared__ __align__(8) uint64_t mbar[2];

    const int tid  = threadIdx.x;
    const int b    = blockIdx.x / RANKS;
    const int rank = blockIdx.x % RANKS;
    const int j    = tid;              // global post-neuron handled by this thread
    const int dest = j >> 4;           // cluster rank owning column j
    const int jj   = j & 15;
    const int j0   = rank * IPC;

    // ---- preload weights into registers (live across entire T loop) ----
    float rs[16], rc[16], rw[16];
    const int iBase = rank * IPC;
    #pragma unroll
    for (int k = 0; k < 16; k++) {
        int idx = (iBase + k) * U_ + j;
        rs[k] = g_rsK[idx]; rc[k] = g_rcK[idx]; rw[k] = g_rwE[idx];
    }
    float ssk[8], sck[8], swe[8];
    const int cBase = rank * CPC;
    #pragma unroll
    for (int k = 0; k < 8; k++) {
        int idx = (cBase + k) * U_ + j;
        ssk[k] = g_ssK[idx]; sck[k] = g_scK[idx]; swe[k] = g_swE[idx];
    }
    // stage my x slice: x[b, :, cBase:cBase+8]
    for (int idx = tid; idx < T_ * CPC; idx += NTH) {
        int t = idx >> 3, k = idx & 7;
        sX[t][k] = x[(b * T_ + t) * C_ + cBase + k];
    }
    if (tid < IPC) {
        int jg = j0 + tid;
        sV[tid]   = h0[b * U_ + jg];
        pCMT[tid] = g_cmt[jg];
        pA[tid]   = g_AA[jg];
        pC[tid]   = g_CC[jg];
        pOW[tid]  = ow[jg];
        pOB[tid]  = ob[jg];
    }
    const uint32_t mb0 = smem_u32(&mbar[0]);
    const uint32_t mb1 = smem_u32(&mbar[1]);
    if (tid == 0) {
        mbar_init_(mb0, 1);
        mbar_init_(mb1, 1);
        mbar_expect_(mb0, TX_REC + TX_SEN);   // unfold 0 + sensory share the first phase
        mbar_expect_(mb1, TX_REC);
    }
    __syncthreads();
    cluster_sync_();   // all CTAs' mbarriers initialized before anyone stores

    // remote addresses for my partial slot and the dest's mbarriers
    const uint32_t addrP0  = mapa_u32(smem_u32(&sPart[0][jj][rank]), (uint32_t)dest);
    const uint32_t addrP1  = mapa_u32(smem_u32(&sPart[1][jj][rank]), (uint32_t)dest);
    const uint32_t addrSen = mapa_u32(smem_u32(&sSens[jj][rank]),    (uint32_t)dest);
    const uint32_t mbR0    = mapa_u32(mb0, (uint32_t)dest);
    const uint32_t mbR1    = mapa_u32(mb1, (uint32_t)dest);

    uint32_t ph0 = 0, ph1 = 0;     // phase parity trackers (warp 0)
    float sn = 0.f, sd = 0.f;      // sensory sums (warp 0, tid<16)

    for (int t = 0; t < T_; t++) {
        // ---- sensory partials (constant across unfolds; fused into unfold-0's wait) ----
        float xn = 0.f, xd = 0.f;
        #pragma unroll
        for (int k = 0; k < 8; k++) {
            float xv = sX[t][k];
            float e  = ex2f_(fmaf(ssk[k], xv, sck[k]));   // 2^(-arg*log2e) = exp(-arg)
            float r  = rcpf_(1.0f + e);                    // sigmoid
            float p  = swe[k] * r;
            xn += p; xd += fabsf(p);
        }
        st_async_f2(addrSen, xn, xd, mbR0);

        // ---- 6 ODE unfolds ----
        #pragma unroll
        for (int u = 0; u < UNFOLDS; u++) {
            float rn = 0.f, rd = 0.f;
            #pragma unroll
            for (int k = 0; k < 16; k++) {
                float vi = sV[k];                          // broadcast LDS
                float e  = ex2f_(fmaf(rs[k], vi, rc[k]));
                float r  = rcpf_(1.0f + e);
                float p  = rw[k] * r;
                rn += p; rd += fabsf(p);
            }
            if ((u & 1) == 0) st_async_f2(addrP0, rn, rd, mbR0);
            else              st_async_f2(addrP1, rn, rd, mbR1);

            if (tid < 32) {                                // warp 0 owns the wait + finalize
                if ((u & 1) == 0) {
                    mbar_wait_(mb0, ph0); ph0 ^= 1;
                    if (tid == 0) mbar_expect_(mb0, (u == 4) ? (TX_REC + TX_SEN) : TX_REC);
                } else {
                    mbar_wait_(mb1, ph1); ph1 ^= 1;
                    if (tid == 0) mbar_expect_(mb1, TX_REC);
                }
                if (tid < IPC) {
                    if (u == 0) {                          // fold in fresh sensory sums
                        const float4* sb = (const float4*)&sSens[tid][0];
                        float4 a0 = sb[0], a1 = sb[1], a2 = sb[2], a3 = sb[3];
                        sn = (a0.x + a0.z) + (a1.x + a1.z) + (a2.x + a2.z) + (a3.x + a3.z);
                        sd = (a0.y + a0.w) + (a1.y + a1.w) + (a2.y + a2.w) + (a3.y + a3.w);
                    }
                    const float4* pb = (const float4*)&sPart[u & 1][tid][0];
                    float4 c0 = pb[0], c1 = pb[1], c2 = pb[2], c3 = pb[3];
                    float n = sn + (c0.x + c0.z) + (c1.x + c1.z) + (c2.x + c2.z) + (c3.x + c3.z);
                    float d = sd + (c0.y + c0.w) + (c1.y + c1.w) + (c2.y + c2.w) + (c3.y + c3.w);
                    float vv  = sV[tid];
                    float num = fmaf(pCMT[tid], vv, pC[tid]) + n;
                    float den = pA[tid] + d + EPS_;
                    sV[tid] = num * rcpf_(den);            // fast div in the serial chain
                }
            }
            __syncthreads();                               // publish new v chunk
        }

        // ---- readout for this step ----
        if (tid < IPC) {
            out[(b * T_ + t) * U_ + j0 + tid] = fmaf(sV[tid], pOW[tid], pOB[tid]);
        }
    }
    // ---- h_final appended after readout block ----
    if (tid < IPC) {
        out[B_ * T_ * U_ + b * U_ + j0 + tid] = sV[tid];
    }
}

// ---------------- launch ----------------
extern "C" void kernel_launch(void* const* d_in, const int* in_sizes, int n_in,
                              void* d_out, int out_size)
{
    const float* x     = (const float*)d_in[0];
    const float* h0    = (const float*)d_in[1];
    const float* gleak = (const float*)d_in[2];
    const float* vleak = (const float*)d_in[3];
    const float* cm    = (const float*)d_in[4];
    const float* sigma = (const float*)d_in[5];
    const float* mu    = (const float*)d_in[6];
    const float* w     = (const float*)d_in[7];
    const float* erev  = (const float*)d_in[8];
    const float* ssig  = (const float*)d_in[9];
    const float* smu   = (const float*)d_in[10];
    const float* sw    = (const float*)d_in[11];
    const float* serev = (const float*)d_in[12];
    const float* iw    = (const float*)d_in[13];
    const float* ib    = (const float*)d_in[14];
    const float* ow    = (const float*)d_in[15];
    const float* ob    = (const float*)d_in[16];

    ltc_prep<<<64, 256>>>(sigma, mu, w, erev, ssig, smu, sw, serev, iw, ib, gleak, vleak, cm);
    ltc_main<<<B_ * RANKS, NTH>>>(x, h0, ow, ob, (float*)d_out);
}

// round 4
// speedup vs baseline: 1.8167x; 1.3486x over previous
#include <cuda_runtime.h>
#include <cstdint>

#define U_ 128
#define C_ 64
#define B_ 16
#define T_ 128
#define RANKS 8          // CTAs per cluster (one cluster per batch)
#define JPC 16           // post-neurons owned per CTA
#define LPJ 8            // lanes (threads) per post-neuron
#define IPL 16           // pre-neurons per lane (128 / 8)
#define CPL 8            // sensory channels per lane (64 / 8)
#define NTH 128
#define UNFOLDS 6
#define EPS_ 1e-8f
#define TX_V 512u        // bytes per v-set arriving at each CTA: 128 * 4B

// ---------------- device scratch (no allocations allowed) ----------------
__device__ float g_rsK[U_*U_];   //  sigma * 0.5
__device__ float g_rcK[U_*U_];   // -sigma * mu * 0.5
__device__ float g_rwE[U_*U_];   //  softplus(w) * erev * 0.5
__device__ float g_ssK[C_*U_];   //  ssigma * iw * 0.5
__device__ float g_scK[C_*U_];   //  ssigma * (ib - smu) * 0.5
__device__ float g_swE[C_*U_];   //  softplus(sw) * serev * 0.5
__device__ float g_cmt[U_];      //  softplus(cm) * 6
__device__ float g_AA[U_];       //  cmt + softplus(gleak)
__device__ float g_CC[U_];       //  softplus(gleak) * vleak

__device__ __forceinline__ float softplus_f(float x) {
    return fmaxf(x, 0.0f) + log1pf(expf(-fabsf(x)));
}

__global__ void ltc_prep(const float* __restrict__ sigma, const float* __restrict__ mu,
                         const float* __restrict__ w,     const float* __restrict__ erev,
                         const float* __restrict__ ssig,  const float* __restrict__ smu,
                         const float* __restrict__ sw,    const float* __restrict__ serev,
                         const float* __restrict__ iw,    const float* __restrict__ ib,
                         const float* __restrict__ gleak, const float* __restrict__ vleak,
                         const float* __restrict__ cm)
{
    int idx = blockIdx.x * blockDim.x + threadIdx.x;
    if (idx < U_*U_) {
        float sg = sigma[idx];
        g_rsK[idx] =  sg * 0.5f;
        g_rcK[idx] = -sg * mu[idx] * 0.5f;
        g_rwE[idx] =  softplus_f(w[idx]) * erev[idx] * 0.5f;
    }
    if (idx < C_*U_) {
        int c = idx / U_;
        float sg = ssig[idx];
        g_ssK[idx] = sg * iw[c] * 0.5f;
        g_scK[idx] = sg * (ib[c] - smu[idx]) * 0.5f;
        g_swE[idx] = softplus_f(sw[idx]) * serev[idx] * 0.5f;
    }
    if (idx < U_) {
        float gl  = softplus_f(gleak[idx]);
        float cmt = softplus_f(cm[idx]) * (float)UNFOLDS;
        g_cmt[idx] = cmt;
        g_AA[idx]  = cmt + gl;
        g_CC[idx]  = gl * vleak[idx];
    }
}

// ---------------- PTX helpers ----------------
__device__ __forceinline__ uint32_t smem_u32(const void* p) {
    uint32_t a;
    asm("{ .reg .u64 t; cvta.to.shared.u64 t, %1; cvt.u32.u64 %0, t; }" : "=r"(a) : "l"(p));
    return a;
}
__device__ __forceinline__ uint32_t mapa_u32(uint32_t a, uint32_t r) {
    uint32_t o;
    asm("mapa.shared::cluster.u32 %0, %1, %2;" : "=r"(o) : "r"(a), "r"(r));
    return o;
}
__device__ __forceinline__ void cluster_sync_() {
    asm volatile("barrier.cluster.arrive.aligned;" ::: "memory");
    asm volatile("barrier.cluster.wait.aligned;"   ::: "memory");
}
__device__ __forceinline__ float tanhf_a(float x) { float y; asm("tanh.approx.f32 %0, %1;" : "=f"(y) : "f"(x)); return y; }
__device__ __forceinline__ float rcpf_(float x)   { float y; asm("rcp.approx.f32 %0, %1;"  : "=f"(y) : "f"(x)); return y; }

__device__ __forceinline__ void mbar_init_(uint32_t mb, uint32_t cnt) {
    asm volatile("mbarrier.init.shared.b64 [%0], %1;" :: "r"(mb), "r"(cnt) : "memory");
}
__device__ __forceinline__ void mbar_expect_(uint32_t mb, uint32_t bytes) {
    asm volatile("mbarrier.arrive.expect_tx.shared.b64 _, [%0], %1;" :: "r"(mb), "r"(bytes) : "memory");
}
__device__ __forceinline__ void mbar_wait_(uint32_t mb, uint32_t parity) {
    uint32_t done;
    asm volatile(
        "{\n\t.reg .pred p;\n\t"
        "mbarrier.try_wait.parity.acquire.cta.shared::cta.b64 p, [%1], %2;\n\t"
        "selp.b32 %0, 1, 0, p;\n\t}"
        : "=r"(done) : "r"(mb), "r"(parity) : "memory");
    if (!done) {
        asm volatile(
            "{\n\t.reg .pred P1;\n\t"
            "WL_%=:\n\t"
            "mbarrier.try_wait.parity.acquire.cta.shared::cta.b64 P1, [%0], %1, 0x989680;\n\t"
            "@P1 bra.uni WD_%=;\n\t"
            "bra.uni WL_%=;\n\t"
            "WD_%=:\n\t}"
            :: "r"(mb), "r"(parity) : "memory");
    }
}
// async 4-byte store into a peer CTA's SMEM, tx-counted on the peer's mbarrier
__device__ __forceinline__ void st_async_f32(uint32_t addr, float v, uint32_t mb) {
    asm volatile("st.async.shared::cluster.mbarrier::complete_tx::bytes.b32 [%0], %1, [%2];"
                 :: "r"(addr), "f"(v), "r"(mb) : "memory");
}

// ---------------- main kernel: one cluster (8 CTAs) per batch ----------------
// CTA `rank` owns post-neurons j in [rank*16, rank*16+16): full i-reduction is LOCAL.
// Only the finished v values cross the cluster (st.async -> peers' sV buffers).
__global__ void __cluster_dims__(RANKS, 1, 1) __launch_bounds__(NTH, 1)
ltc_main(const float* __restrict__ x, const float* __restrict__ h0,
         const float* __restrict__ ow, const float* __restrict__ ob,
         float* __restrict__ out)
{
    __shared__ float sV[3][U_];        // triple-buffered v-sets
    __shared__ float sX[T_][C_];       // full input slice for this batch (32 KB)
    __shared__ __align__(8) uint64_t mbar[3];

    const int tid  = threadIdx.x;
    const int b    = blockIdx.x / RANKS;
    const int rank = blockIdx.x % RANKS;
    const int jj   = tid >> 3;         // local post-neuron (0..15)
    const int s    = tid & 7;          // lane within j-group (0..7)
    const int jg   = rank * JPC + jj;  // global post-neuron

    // ---- weights into registers (live across entire run) ----
    float rs[IPL], rc[IPL], rw[IPL];
    #pragma unroll
    for (int k = 0; k < IPL; k++) {
        int idx = (s * IPL + k) * U_ + jg;
        rs[k] = g_rsK[idx]; rc[k] = g_rcK[idx]; rw[k] = g_rwE[idx];
    }
    float ssk[CPL], sck[CPL], swe[CPL];
    #pragma unroll
    for (int k = 0; k < CPL; k++) {
        int idx = (s * CPL + k) * U_ + jg;
        ssk[k] = g_ssK[idx]; sck[k] = g_scK[idx]; swe[k] = g_swE[idx];
    }
    const float pcm = g_cmt[jg], pa = g_AA[jg], pcc = g_CC[jg];
    const float pow_ = ow[jg], pob_ = ob[jg];

    // stage x[b] into SMEM (float4)
    {
        const float4* xg = (const float4*)(x + (size_t)b * T_ * C_);
        float4* xs = (float4*)&sX[0][0];
        #pragma unroll 4
        for (int i = tid; i < T_ * C_ / 4; i += NTH) xs[i] = xg[i];
    }
    sV[0][tid] = h0[b * U_ + tid];     // set 0

    const uint32_t mbL[3] = { smem_u32(&mbar[0]), smem_u32(&mbar[1]), smem_u32(&mbar[2]) };
    if (tid == 0) {
        #pragma unroll
        for (int m = 0; m < 3; m++) { mbar_init_(mbL[m], 1); mbar_expect_(mbL[m], TX_V); }
    }
    __syncthreads();
    cluster_sync_();                   // all mbarriers armed before any st.async

    // remote addresses: lane s delivers this group's v to rank s
    uint32_t addrV[3], mbR[3];
    #pragma unroll
    for (int m = 0; m < 3; m++) {
        addrV[m] = mapa_u32(smem_u32(&sV[m][jg]), (uint32_t)s);
        mbR[m]   = mapa_u32(mbL[m], (uint32_t)s);
    }

    uint32_t ph[3] = { 0, 0, 0 };
    float vlast = 0.f;

    for (int t = 0; t < T_; t++) {
        // ---- sensory partials (local; hidden in previous broadcast's transit) ----
        float xn = 0.f, xd = 0.f;
        #pragma unroll
        for (int k = 0; k < CPL; k++) {
            float xv = sX[t][s * CPL + k];
            float tt = tanhf_a(fmaf(ssk[k], xv, sck[k]));
            float p  = fmaf(swe[k], tt, swe[k]);   // w_pos*erev*sigmoid
            xn += p; xd += fabsf(p);
        }

        #pragma unroll
        for (int u = 0; u < UNFOLDS; u++) {
            const int m  = u % 3;            // buffer holding v-set 6t+u
            const int mw = (u + 1) % 3;      // buffer receiving v-set 6t+u+1
            if (u != 0 || t != 0) {
                mbar_wait_(mbL[m], ph[m]); ph[m] ^= 1;
                if (tid == 0) mbar_expect_(mbL[m], TX_V);   // re-arm for its next phase
            }
            // recurrent partial over my 16 pre-neurons (sensory folded in)
            float rn = xn, rd = xd;
            const float4* vb = (const float4*)&sV[m][s * IPL];
            float4 v0 = vb[0], v1 = vb[1], v2 = vb[2], v3 = vb[3];
            const float vi[IPL] = { v0.x,v0.y,v0.z,v0.w, v1.x,v1.y,v1.z,v1.w,
                                    v2.x,v2.y,v2.z,v2.w, v3.x,v3.y,v3.z,v3.w };
            #pragma unroll
            for (int k = 0; k < IPL; k++) {
                float tt = tanhf_a(fmaf(rs[k], vi[k], rc[k]));
                float p  = fmaf(rw[k], tt, rw[k]);
                rn += p; rd += fabsf(p);
            }
            // butterfly over the 8-lane group (all lanes end with full sums)
            #pragma unroll
            for (int d = 4; d >= 1; d >>= 1) {
                rn += __shfl_xor_sync(0xffffffffu, rn, d);
                rd += __shfl_xor_sync(0xffffffffu, rd, d);
            }
            // finalize v (every lane, redundantly)
            float vv   = sV[m][jg];
            float num  = fmaf(pcm, vv, pcc) + rn;
            float den  = pa + rd + EPS_;
            float vnew = num * rcpf_(den);
            // broadcast: lane s sends to rank s (skip very last set: consumed from regs)
            if (t != T_ - 1 || u != UNFOLDS - 1)
                st_async_f32(addrV[mw], vnew, mbR[mw]);
            if (u == UNFOLDS - 1) {
                if (s == 0) out[((size_t)b * T_ + t) * U_ + jg] = fmaf(vnew, pow_, pob_);
                vlast = vnew;
            }
        }
    }
    if (s == 0) out[(size_t)B_ * T_ * U_ + b * U_ + jg] = vlast;   // h_final
    cluster_sync_();
}

// ---------------- launch ----------------
extern "C" void kernel_launch(void* const* d_in, const int* in_sizes, int n_in,
                              void* d_out, int out_size)
{
    const float* x     = (const float*)d_in[0];
    const float* h0    = (const float*)d_in[1];
    const float* gleak = (const float*)d_in[2];
    const float* vleak = (const float*)d_in[3];
    const float* cm    = (const float*)d_in[4];
    const float* sigma = (const float*)d_in[5];
    const float* mu    = (const float*)d_in[6];
    const float* w     = (const float*)d_in[7];
    const float* erev  = (const float*)d_in[8];
    const float* ssig  = (const float*)d_in[9];
    const float* smu   = (const float*)d_in[10];
    const float* sw    = (const float*)d_in[11];
    const float* serev = (const float*)d_in[12];
    const float* iw    = (const float*)d_in[13];
    const float* ib    = (const float*)d_in[14];
    const float* ow    = (const float*)d_in[15];
    const float* ob    = (const float*)d_in[16];

    ltc_prep<<<64, 256>>>(sigma, mu, w, erev, ssig, smu, sw, serev, iw, ib, gleak, vleak, cm);
    ltc_main<<<B_ * RANKS, NTH>>>(x, h0, ow, ob, (float*)d_out);
}